// round 14
// baseline (speedup 1.0000x reference)
#include <cuda_runtime.h>
#include <cuda_bf16.h>
#include <math.h>
#include <stdint.h>

// Problem constants
#define B_SZ   8
#define L_SEQ  4096
#define D_MODEL 512
#define NC     128
#define NSTATE 64
#define NTAPS  32
#define M_ROWS (B_SZ * L_SEQ)   // 32768

// Scratch. g_z, g_y, g_wti, g_wto are stored with a per-8-group k-interleave
// [k0 k4 k1 k5 k2 k6 k3 k7] so GEMM fragment loads are LDS.64.
__device__ float g_z  [M_ROWS * D_MODEL];   // LN output (tf32, k-interleaved)
__device__ float g_z1 [M_ROWS * D_MODEL];   // in-proj output (natural layout)
__device__ float g_y  [M_ROWS * D_MODEL];   // FIR output (tf32, k-interleaved)
__device__ float g_k  [NC * NTAPS];
__device__ float g_wti[D_MODEL * D_MODEL];  // Win^T  (tf32, k-interleaved)
__device__ float g_wto[D_MODEL * D_MODEL];  // Wout^T (tf32, k-interleaved)

// ---------------------------------------------------------------------------
// Helpers
// ---------------------------------------------------------------------------
__device__ __forceinline__ float to_tf32(float f) {
    uint32_t u;
    asm("cvt.rna.tf32.f32 %0, %1;" : "=r"(u) : "f"(f));
    return __uint_as_float(u);
}
__device__ __forceinline__ uint32_t smem_u32(const void* p) {
    uint32_t a;
    asm("{ .reg .u64 t; cvta.to.shared.u64 t, %1; cvt.u32.u64 %0, t; }" : "=r"(a) : "l"(p));
    return a;
}
__device__ __forceinline__ void cp16(uint32_t dst, const void* src) {
    asm volatile("cp.async.cg.shared.global [%0], [%1], 16;" :: "r"(dst), "l"(src));
}
#define CP_COMMIT() asm volatile("cp.async.commit_group;" ::: "memory")
#define CP_WAIT(n)  asm volatile("cp.async.wait_group %0;" :: "n"(n) : "memory")

// m16n8k8 tf32 warp MMA
__device__ __forceinline__ void mma_tf32(float c[4],
                                         float a0, float a1, float a2, float a3,
                                         float b0, float b1)
{
    asm volatile(
        "mma.sync.aligned.m16n8k8.row.col.f32.tf32.tf32.f32 "
        "{%0,%1,%2,%3}, {%4,%5,%6,%7}, {%8,%9}, {%0,%1,%2,%3};"
        : "+f"(c[0]), "+f"(c[1]), "+f"(c[2]), "+f"(c[3])
        : "r"(__float_as_uint(a0)), "r"(__float_as_uint(a1)),
          "r"(__float_as_uint(a2)), "r"(__float_as_uint(a3)),
          "r"(__float_as_uint(b0)), "r"(__float_as_uint(b1)));
}

// f32x2 packed math
__device__ __forceinline__ uint64_t pk2(float a, float b) {
    uint64_t r; asm("mov.b64 %0, {%1, %2};" : "=l"(r) : "f"(a), "f"(b)); return r;
}
__device__ __forceinline__ void upk2(uint64_t v, float& a, float& b) {
    asm("mov.b64 {%0, %1}, %2;" : "=f"(a), "=f"(b) : "l"(v));
}
__device__ __forceinline__ uint64_t addx2(uint64_t a, uint64_t b) {
    uint64_t r; asm("add.rn.f32x2 %0, %1, %2;" : "=l"(r) : "l"(a), "l"(b)); return r;
}
__device__ __forceinline__ uint64_t mulx2(uint64_t a, uint64_t b) {
    uint64_t r; asm("mul.rn.f32x2 %0, %1, %2;" : "=l"(r) : "l"(a), "l"(b)); return r;
}
__device__ __forceinline__ uint64_t fmax2(uint64_t a, uint64_t b, uint64_t c) {
    uint64_t r; asm("fma.rn.f32x2 %0, %1, %2, %3;" : "=l"(r) : "l"(a), "l"(b), "l"(c)); return r;
}

// ---------------------------------------------------------------------------
// Combined prep kernel:
//   [0, 16384)        LayerNorm, 2 rows/block -> g_z (tf32, k-interleaved)
//   [16384, 16896)    Win^T / Wout^T transpose + tf32 round (k-interleaved)
//   [16896, 16912)    FIR taps
// ---------------------------------------------------------------------------
#define PREP_LN    16384
#define PREP_WT    (PREP_LN + 512)
#define PREP_TOTAL (PREP_WT + 16)

__global__ __launch_bounds__(256)
void prep_kernel(const float* __restrict__ x,
                 const float* __restrict__ gam, const float* __restrict__ bet,
                 const float* __restrict__ Win, const float* __restrict__ Wout,
                 const float* __restrict__ lre, const float* __restrict__ lim,
                 const float* __restrict__ Bm,  const float* __restrict__ cre,
                 const float* __restrict__ cim)
{
    int bid = blockIdx.x;
    int tid = threadIdx.x;

    if (bid < PREP_LN) {
        int half = tid >> 7;
        int t    = tid & 127;
        int row  = bid * 2 + half;
        float4 v = ((const float4*)(x + (size_t)row * D_MODEL))[t];
        float s  = v.x + v.y + v.z + v.w;
        float sq = v.x*v.x + v.y*v.y + v.z*v.z + v.w*v.w;
        #pragma unroll
        for (int off = 16; off > 0; off >>= 1) {
            s  += __shfl_xor_sync(0xFFFFFFFFu, s,  off);
            sq += __shfl_xor_sync(0xFFFFFFFFu, sq, off);
        }
        __shared__ float ss[8], ssq[8];
        int warp = tid >> 5, lane = tid & 31;
        if (lane == 0) { ss[warp] = s; ssq[warp] = sq; }
        __syncthreads();
        int w0 = half * 4;
        float tots = ss[w0] + ss[w0+1] + ss[w0+2] + ss[w0+3];
        float totq = ssq[w0] + ssq[w0+1] + ssq[w0+2] + ssq[w0+3];
        float mu  = tots * (1.0f / D_MODEL);
        float var = totq * (1.0f / D_MODEL) - mu * mu;
        float inv = rsqrtf(var + 1e-5f);
        float4 gg = ((const float4*)gam)[t];
        float4 bb = ((const float4*)bet)[t];
        float4 o;
        o.x = to_tf32((v.x - mu) * inv * gg.x + bb.x);
        o.y = to_tf32((v.y - mu) * inv * gg.y + bb.y);
        o.z = to_tf32((v.z - mu) * inv * gg.z + bb.z);
        o.w = to_tf32((v.w - mu) * inv * gg.w + bb.w);
        // k-interleave within 8-groups via lane-pair shuffles
        float rx = __shfl_xor_sync(0xFFFFFFFFu, o.x, 1);
        float ry = __shfl_xor_sync(0xFFFFFFFFu, o.y, 1);
        float rz = __shfl_xor_sync(0xFFFFFFFFu, o.z, 1);
        float rw = __shfl_xor_sync(0xFFFFFFFFu, o.w, 1);
        float4 st = ((t & 1) == 0) ? make_float4(o.x, rx, o.y, ry)
                                   : make_float4(rz, o.z, rw, o.w);
        ((float4*)(g_z + (size_t)row * D_MODEL))[t] = st;
    } else if (bid < PREP_WT) {
        int ti = bid - PREP_LN;
        const float* W;
        float* Wt;
        if (ti < 256) { W = Win;  Wt = g_wti; }
        else          { W = Wout; Wt = g_wto; ti -= 256; }
        int n0 = (ti & 15) * 32, k0 = (ti >> 4) * 32;
        __shared__ float tile[32][33];
        int tx = tid & 31, ty = tid >> 5;   // 32 x 8
        #pragma unroll
        for (int j = 0; j < 32; j += 8)
            tile[ty + j][tx] = W[(size_t)(k0 + ty + j) * D_MODEL + n0 + tx];
        __syncthreads();
        // permuted k position: within 8-group, i -> (i<4) ? 2i : 2(i-4)+1
        int i8  = tx & 7;
        int kp  = k0 + (tx & ~7) + ((i8 < 4) ? 2 * i8 : 2 * (i8 - 4) + 1);
        #pragma unroll
        for (int j = 0; j < 32; j += 8)
            Wt[(size_t)(n0 + ty + j) * D_MODEL + kp] = to_tf32(tile[tx][ty + j]);
    } else {
        int c = (bid - PREP_WT) * 8 + (tid >> 5);
        int tau = tid & 31;
        float ft = (float)tau;
        float acc = 0.0f;
        #pragma unroll 8
        for (int n = 0; n < NSTATE; n++) {
            int idx = c * NSTATE + n;
            float re = lre[idx], im = lim[idx], bn = Bm[idx];
            float cr = cre[idx] * bn, ci = cim[idx] * bn;
            float s, co;
            sincosf(im * ft, &s, &co);
            acc += expf(re * ft) * (cr * co - ci * s);
        }
        g_k[c * NTAPS + tau] = acc;
    }
}

// ---------------------------------------------------------------------------
// Warp-MMA tf32 GEMM. CTA tile 128x128, BK=32, 8 warps (2m x 4n), m16n8k8,
// 2 CTAs/SM (16 warps). Pair-block smem layout: stage = [pg][row] float2-pairs,
// block stride 2112B (64B pad) -> conflict-free LDS.64/STS.128 AND fully
// additive addressing: every fragment/staging address = base reg + immediate.
// 3-stage cp.async pipeline, literal buffer offsets, single barrier per stage.
// ---------------------------------------------------------------------------
__device__ __forceinline__ float gelu_exact(float v) {
    return 0.5f * v * (1.0f + erff(v * 0.70710678118654752f));
}

#define PG_STRIDE 2112                    // 128 rows x 16B + 64B pad
#define HALF_TILE (8 * PG_STRIDE)         // 16896B (A or B region)
#define STG_BYTES (2 * HALF_TILE)         // 33792B per stage
#define NSTAGE 3
#define GEMM_SMEM (NSTAGE * STG_BYTES)    // 101376B

template<int EPI>
__global__ __launch_bounds__(256, 2)
void gemm_mma(const float* __restrict__ A, const float* __restrict__ Bt,
              const float* __restrict__ bias, const float* __restrict__ resid,
              float* __restrict__ C)
{
    extern __shared__ __align__(16) char sm[];
    uint32_t ubase = smem_u32(sm);

    int tid = threadIdx.x;
    int lane = tid & 31;
    int wid  = tid >> 5;
    int wm = wid >> 2;       // 0..1
    int wn = wid & 3;        // 0..3
    int g  = lane >> 2;      // 0..7
    int t4 = lane & 3;       // 0..3

    // thread-fixed fragment bases (all further deltas are immediates)
    uint32_t fbase = (uint32_t)((t4 >> 1) * PG_STRIDE + ((t4 & 1) << 3));
    uint32_t abase = fbase + (uint32_t)((wm * 64 + g) * 16);
    uint32_t bbase = fbase + (uint32_t)((wn * 32 + g) * 16) + HALF_TILE;

    int bn = blockIdx.x, bm = blockIdx.y;
    int rowA = bm * 128, rowB = bn * 128;

    // staging: thread covers rows rowt+32i (i=0..3) of pair-group pg
    int rowt = (tid & 7) + ((tid >> 6) & 3) * 8;   // 0..31
    int pg   = (tid >> 3) & 7;
    uint32_t so = ubase + (uint32_t)(pg * PG_STRIDE + rowt * 16);
    const float* aP = A  + (((size_t)(rowA + rowt)) << 9) + (pg << 2);
    const float* bP = Bt + (((size_t)(rowB + rowt)) << 9) + (pg << 2);

    float acc[4][4][4];
    #pragma unroll
    for (int mt = 0; mt < 4; mt++)
        #pragma unroll
        for (int nt = 0; nt < 4; nt++)
            #pragma unroll
            for (int q = 0; q < 4; q++) acc[mt][nt][q] = 0.0f;

    // prefetch one stage into buffer at byte offset BB; advances aP/bP by 32
    auto gprefetch = [&](uint32_t BB) {
        cp16(so + BB,                    aP);
        cp16(so + BB +  512,             aP + 16384);
        cp16(so + BB + 1024,             aP + 32768);
        cp16(so + BB + 1536,             aP + 49152);
        cp16(so + BB + HALF_TILE,        bP);
        cp16(so + BB + HALF_TILE +  512, bP + 16384);
        cp16(so + BB + HALF_TILE + 1024, bP + 32768);
        cp16(so + BB + HALF_TILE + 1536, bP + 49152);
        aP += 32; bP += 32;
        CP_COMMIT();
    };

    auto gcompute = [&](const char* cbuf) {
        #pragma unroll
        for (int ks = 0; ks < 4; ks++) {
            float2 a0[4], a1[4], bb[4];
            #pragma unroll
            for (int mt = 0; mt < 4; mt++) {
                a0[mt] = *(const float2*)(cbuf + abase + ks * 4224 + mt * 256);
                a1[mt] = *(const float2*)(cbuf + abase + ks * 4224 + mt * 256 + 128);
            }
            #pragma unroll
            for (int nt = 0; nt < 4; nt++)
                bb[nt] = *(const float2*)(cbuf + bbase + ks * 4224 + nt * 128);
            #pragma unroll
            for (int mt = 0; mt < 4; mt++)
                #pragma unroll
                for (int nt = 0; nt < 4; nt++)
                    mma_tf32(acc[mt][nt], a0[mt].x, a1[mt].x, a0[mt].y, a1[mt].y,
                             bb[nt].x, bb[nt].y);
        }
    };

    // prologue: stage 0 -> buf0, stage 1 -> buf1
    gprefetch(0);
    gprefetch(STG_BYTES);

    // stages 0..11: 4 x (buf0, buf1, buf2), prefetching s+2 with literal bufs
    #pragma unroll 1
    for (int it = 0; it < 4; it++) {
        CP_WAIT(1); __syncthreads(); gprefetch(2 * STG_BYTES); gcompute(sm);
        CP_WAIT(1); __syncthreads(); gprefetch(0);             gcompute(sm + STG_BYTES);
        CP_WAIT(1); __syncthreads(); gprefetch(STG_BYTES);     gcompute(sm + 2 * STG_BYTES);
    }
    // s=12..15: two more prefetches then drain
    CP_WAIT(1); __syncthreads(); gprefetch(2 * STG_BYTES); gcompute(sm);
    CP_WAIT(1); __syncthreads(); gprefetch(0);             gcompute(sm + STG_BYTES);
    CP_WAIT(1); __syncthreads();                           gcompute(sm + 2 * STG_BYTES);
    CP_WAIT(0); __syncthreads();                           gcompute(sm);

    // epilogue
    #pragma unroll
    for (int mt = 0; mt < 4; mt++) {
        size_t r0 = (size_t)rowA + wm * 64 + mt * 16 + g;
        size_t r1 = r0 + 8;
        #pragma unroll
        for (int nt = 0; nt < 4; nt++) {
            int col = bn * 128 + wn * 32 + nt * 8 + 2 * t4;
            float b0 = bias[col], b1 = bias[col + 1];
            float v0 = acc[mt][nt][0] + b0;
            float v1 = acc[mt][nt][1] + b1;
            float v2 = acc[mt][nt][2] + b0;
            float v3 = acc[mt][nt][3] + b1;
            if (EPI == 1) {
                const float* rr0 = resid + r0 * D_MODEL + col;
                const float* rr1 = resid + r1 * D_MODEL + col;
                v0 = rr0[0] + gelu_exact(v0);
                v1 = rr0[1] + gelu_exact(v1);
                v2 = rr1[0] + gelu_exact(v2);
                v3 = rr1[1] + gelu_exact(v3);
            }
            *(float2*)(C + r0 * D_MODEL + col) = make_float2(v0, v1);
            *(float2*)(C + r1 * D_MODEL + col) = make_float2(v2, v3);
        }
    }
}

// ---------------------------------------------------------------------------
// Bidirectional 32-tap FIR + D skip. Block = 8 chunks x 256 rows, 256 threads
// (thread = 1 chunk x 8 sliding-window rows). Coalesced 128B loads, conflict-
// free LDS.128, lane-pair shuffle assembles the k-interleave in registers ->
// one full-sector STG.128 per row.
// ---------------------------------------------------------------------------
#define FT_BLK 256
#define FIR_ROWS (FT_BLK + 2 * NTAPS + 1)   // 321

__global__ __launch_bounds__(256)
void fir_kernel(const float* __restrict__ Dvec)
{
    int c0 = blockIdx.y * 8;
    int b  = blockIdx.z;
    int t0 = blockIdx.x * FT_BLK;
    int tid = threadIdx.x;

    __shared__ float4 su[FIR_ROWS][8];   // [local row][chunk]
    __shared__ float  sk[8][33];         // padded taps

    const float4* u4 = (const float4*)g_z1;
    for (int slot = tid; slot < FIR_ROWS * 8; slot += 256) {
        int row = slot >> 3, cc = slot & 7;
        int t = t0 - 32 + row;
        float4 v = make_float4(0.f, 0.f, 0.f, 0.f);
        if (t >= 0 && t < L_SEQ) v = u4[((size_t)b * L_SEQ + t) * NC + c0 + cc];
        su[row][cc] = v;
    }
    {
        int cc = tid >> 5, tau = tid & 31;
        sk[cc][tau] = g_k[(c0 + cc) * NTAPS + tau];
    }
    __syncthreads();

    int c  = tid & 7;          // chunk within group
    int rg = tid >> 3;         // row group 0..31
    int w  = rg * 8;           // first output row (local)

    float4 F[8], Bw[8];
    #pragma unroll
    for (int r = 0; r < 8; r++) { F[r] = su[w + 32 + r][c]; Bw[r] = su[w + 33 + r][c]; }

    float dv = Dvec[c0 + c];
    uint64_t dv2 = pk2(dv, dv);
    uint64_t aL[8], aH[8];
    #pragma unroll
    for (int r = 0; r < 8; r++) {
        aL[r] = mulx2(dv2, pk2(F[r].x, F[r].y));
        aH[r] = mulx2(dv2, pk2(F[r].z, F[r].w));
    }

    #pragma unroll
    for (int tau = 0; tau < NTAPS; tau++) {
        float kt = sk[c][tau];
        uint64_t k2 = pk2(kt, kt);
        #pragma unroll
        for (int r = 0; r < 8; r++) {
            uint64_t sL = addx2(pk2(F[r].x, F[r].y), pk2(Bw[r].x, Bw[r].y));
            uint64_t sH = addx2(pk2(F[r].z, F[r].w), pk2(Bw[r].z, Bw[r].w));
            aL[r] = fmax2(k2, sL, aL[r]);
            aH[r] = fmax2(k2, sH, aH[r]);
        }
        #pragma unroll
        for (int r = 7; r > 0; r--) F[r] = F[r - 1];
        F[0] = su[w + 31 - tau][c];
        #pragma unroll
        for (int r = 0; r < 7; r++) Bw[r] = Bw[r + 1];
        Bw[7] = su[w + 41 + tau][c];
    }

    // interleaved store: lane pairs (c, c^1) exchange halves, one STG.128/row
    float4* ybase = (float4*)(g_y) + (size_t)(c0 >> 1) * 2 + (c >> 1) * 2 + (c & 1);
    #pragma unroll
    for (int r = 0; r < 8; r++) {
        float4 o;
        upk2(aL[r], o.x, o.y);
        upk2(aH[r], o.z, o.w);
        o.x = to_tf32(o.x); o.y = to_tf32(o.y); o.z = to_tf32(o.z); o.w = to_tf32(o.w);
        float rx = __shfl_xor_sync(0xFFFFFFFFu, o.x, 1);
        float ry = __shfl_xor_sync(0xFFFFFFFFu, o.y, 1);
        float rz = __shfl_xor_sync(0xFFFFFFFFu, o.z, 1);
        float rw = __shfl_xor_sync(0xFFFFFFFFu, o.w, 1);
        float4 st = ((c & 1) == 0) ? make_float4(o.x, rx, o.y, ry)
                                   : make_float4(rz, o.z, rw, o.w);
        ybase[((size_t)b * L_SEQ + t0 + w + r) * (D_MODEL / 4)] = st;
    }
}

// ---------------------------------------------------------------------------
// Launch
// ---------------------------------------------------------------------------
extern "C" void kernel_launch(void* const* d_in, const int* in_sizes, int n_in,
                              void* d_out, int out_size)
{
    const float* x    = (const float*)d_in[0];
    const float* ln_g = (const float*)d_in[1];
    const float* ln_b = (const float*)d_in[2];
    const float* Win  = (const float*)d_in[3];
    const float* bin_ = (const float*)d_in[4];
    const float* Wout = (const float*)d_in[5];
    const float* bout = (const float*)d_in[6];
    const float* lre  = (const float*)d_in[7];
    const float* lim  = (const float*)d_in[8];
    const float* Bm   = (const float*)d_in[9];
    const float* cre  = (const float*)d_in[10];
    const float* cim  = (const float*)d_in[11];
    const float* Dvec = (const float*)d_in[12];
    float* out = (float*)d_out;

    float *z, *z1, *y, *wti, *wto;
    cudaGetSymbolAddress((void**)&z,   g_z);
    cudaGetSymbolAddress((void**)&z1,  g_z1);
    cudaGetSymbolAddress((void**)&y,   g_y);
    cudaGetSymbolAddress((void**)&wti, g_wti);
    cudaGetSymbolAddress((void**)&wto, g_wto);

    cudaFuncSetAttribute(gemm_mma<0>, cudaFuncAttributeMaxDynamicSharedMemorySize, GEMM_SMEM);
    cudaFuncSetAttribute(gemm_mma<1>, cudaFuncAttributeMaxDynamicSharedMemorySize, GEMM_SMEM);

    // 1. combined prep: LayerNorm + Win^T + Wout^T + FIR taps
    prep_kernel<<<PREP_TOTAL, 256>>>(x, ln_g, ln_b, Win, Wout, lre, lim, Bm, cre, cim);

    // 2. in-projection: z1 = z @ Win + bin
    gemm_mma<0><<<dim3(4, 256), 256, GEMM_SMEM>>>(z, wti, bin_, nullptr, z1);

    // 3. bidirectional FIR + D skip
    fir_kernel<<<dim3(L_SEQ / FT_BLK, NC / 8, B_SZ), 256>>>(Dvec);

    // 4. out-projection + gelu + residual -> d_out
    gemm_mma<1><<<dim3(4, 256), 256, GEMM_SMEM>>>(y, wto, bout, x, out);
}

// round 15
// speedup vs baseline: 1.5627x; 1.5627x over previous
#include <cuda_runtime.h>
#include <cuda_bf16.h>
#include <math.h>
#include <stdint.h>

// Problem constants
#define B_SZ   8
#define L_SEQ  4096
#define D_MODEL 512
#define NC     128
#define NSTATE 64
#define NTAPS  32
#define M_ROWS (B_SZ * L_SEQ)   // 32768

// Scratch. g_z, g_y, g_wti, g_wto are stored with a per-8-group k-interleave
// [k0 k4 k1 k5 k2 k6 k3 k7] so GEMM fragment loads are LDS.64.
__device__ float g_z  [M_ROWS * D_MODEL];   // LN output (tf32, k-interleaved)
__device__ float g_z1 [M_ROWS * D_MODEL];   // in-proj output (natural layout)
__device__ float g_y  [M_ROWS * D_MODEL];   // FIR output (tf32, k-interleaved)
__device__ float g_k  [NC * NTAPS];
__device__ float g_wti[D_MODEL * D_MODEL];  // Win^T  (tf32, k-interleaved)
__device__ float g_wto[D_MODEL * D_MODEL];  // Wout^T (tf32, k-interleaved)

// ---------------------------------------------------------------------------
// Helpers
// ---------------------------------------------------------------------------
__device__ __forceinline__ float to_tf32(float f) {
    uint32_t u;
    asm("cvt.rna.tf32.f32 %0, %1;" : "=r"(u) : "f"(f));
    return __uint_as_float(u);
}
__device__ __forceinline__ uint32_t smem_u32(const void* p) {
    uint32_t a;
    asm("{ .reg .u64 t; cvta.to.shared.u64 t, %1; cvt.u32.u64 %0, t; }" : "=r"(a) : "l"(p));
    return a;
}
__device__ __forceinline__ void cp16(uint32_t dst, const void* src) {
    asm volatile("cp.async.cg.shared.global [%0], [%1], 16;" :: "r"(dst), "l"(src));
}
#define CP_COMMIT() asm volatile("cp.async.commit_group;" ::: "memory")
#define CP_WAIT(n)  asm volatile("cp.async.wait_group %0;" :: "n"(n) : "memory")

// m16n8k8 tf32 warp MMA
__device__ __forceinline__ void mma_tf32(float c[4],
                                         float a0, float a1, float a2, float a3,
                                         float b0, float b1)
{
    asm volatile(
        "mma.sync.aligned.m16n8k8.row.col.f32.tf32.tf32.f32 "
        "{%0,%1,%2,%3}, {%4,%5,%6,%7}, {%8,%9}, {%0,%1,%2,%3};"
        : "+f"(c[0]), "+f"(c[1]), "+f"(c[2]), "+f"(c[3])
        : "r"(__float_as_uint(a0)), "r"(__float_as_uint(a1)),
          "r"(__float_as_uint(a2)), "r"(__float_as_uint(a3)),
          "r"(__float_as_uint(b0)), "r"(__float_as_uint(b1)));
}

// f32x2 packed math
__device__ __forceinline__ uint64_t pk2(float a, float b) {
    uint64_t r; asm("mov.b64 %0, {%1, %2};" : "=l"(r) : "f"(a), "f"(b)); return r;
}
__device__ __forceinline__ void upk2(uint64_t v, float& a, float& b) {
    asm("mov.b64 {%0, %1}, %2;" : "=f"(a), "=f"(b) : "l"(v));
}
__device__ __forceinline__ uint64_t addx2(uint64_t a, uint64_t b) {
    uint64_t r; asm("add.rn.f32x2 %0, %1, %2;" : "=l"(r) : "l"(a), "l"(b)); return r;
}
__device__ __forceinline__ uint64_t mulx2(uint64_t a, uint64_t b) {
    uint64_t r; asm("mul.rn.f32x2 %0, %1, %2;" : "=l"(r) : "l"(a), "l"(b)); return r;
}
__device__ __forceinline__ uint64_t fmax2(uint64_t a, uint64_t b, uint64_t c) {
    uint64_t r; asm("fma.rn.f32x2 %0, %1, %2, %3;" : "=l"(r) : "l"(a), "l"(b), "l"(c)); return r;
}

// ---------------------------------------------------------------------------
// Combined prep kernel:
//   [0, 16384)        LayerNorm, 2 rows/block -> g_z (tf32, k-interleaved)
//   [16384, 16896)    Win^T / Wout^T transpose + tf32 round (k-interleaved)
//   [16896, 16912)    FIR taps
// ---------------------------------------------------------------------------
#define PREP_LN    16384
#define PREP_WT    (PREP_LN + 512)
#define PREP_TOTAL (PREP_WT + 16)

__global__ __launch_bounds__(256)
void prep_kernel(const float* __restrict__ x,
                 const float* __restrict__ gam, const float* __restrict__ bet,
                 const float* __restrict__ Win, const float* __restrict__ Wout,
                 const float* __restrict__ lre, const float* __restrict__ lim,
                 const float* __restrict__ Bm,  const float* __restrict__ cre,
                 const float* __restrict__ cim)
{
    int bid = blockIdx.x;
    int tid = threadIdx.x;

    if (bid < PREP_LN) {
        int half = tid >> 7;
        int t    = tid & 127;
        int row  = bid * 2 + half;
        float4 v = ((const float4*)(x + (size_t)row * D_MODEL))[t];
        float s  = v.x + v.y + v.z + v.w;
        float sq = v.x*v.x + v.y*v.y + v.z*v.z + v.w*v.w;
        #pragma unroll
        for (int off = 16; off > 0; off >>= 1) {
            s  += __shfl_xor_sync(0xFFFFFFFFu, s,  off);
            sq += __shfl_xor_sync(0xFFFFFFFFu, sq, off);
        }
        __shared__ float ss[8], ssq[8];
        int warp = tid >> 5, lane = tid & 31;
        if (lane == 0) { ss[warp] = s; ssq[warp] = sq; }
        __syncthreads();
        int w0 = half * 4;
        float tots = ss[w0] + ss[w0+1] + ss[w0+2] + ss[w0+3];
        float totq = ssq[w0] + ssq[w0+1] + ssq[w0+2] + ssq[w0+3];
        float mu  = tots * (1.0f / D_MODEL);
        float var = totq * (1.0f / D_MODEL) - mu * mu;
        float inv = rsqrtf(var + 1e-5f);
        float4 gg = ((const float4*)gam)[t];
        float4 bb = ((const float4*)bet)[t];
        float4 o;
        o.x = to_tf32((v.x - mu) * inv * gg.x + bb.x);
        o.y = to_tf32((v.y - mu) * inv * gg.y + bb.y);
        o.z = to_tf32((v.z - mu) * inv * gg.z + bb.z);
        o.w = to_tf32((v.w - mu) * inv * gg.w + bb.w);
        // k-interleave within 8-groups via lane-pair shuffles
        float rx = __shfl_xor_sync(0xFFFFFFFFu, o.x, 1);
        float ry = __shfl_xor_sync(0xFFFFFFFFu, o.y, 1);
        float rz = __shfl_xor_sync(0xFFFFFFFFu, o.z, 1);
        float rw = __shfl_xor_sync(0xFFFFFFFFu, o.w, 1);
        float4 st = ((t & 1) == 0) ? make_float4(o.x, rx, o.y, ry)
                                   : make_float4(rz, o.z, rw, o.w);
        ((float4*)(g_z + (size_t)row * D_MODEL))[t] = st;
    } else if (bid < PREP_WT) {
        int ti = bid - PREP_LN;
        const float* W;
        float* Wt;
        if (ti < 256) { W = Win;  Wt = g_wti; }
        else          { W = Wout; Wt = g_wto; ti -= 256; }
        int n0 = (ti & 15) * 32, k0 = (ti >> 4) * 32;
        __shared__ float tile[32][33];
        int tx = tid & 31, ty = tid >> 5;   // 32 x 8
        #pragma unroll
        for (int j = 0; j < 32; j += 8)
            tile[ty + j][tx] = W[(size_t)(k0 + ty + j) * D_MODEL + n0 + tx];
        __syncthreads();
        // permuted k position: within 8-group, i -> (i<4) ? 2i : 2(i-4)+1
        int i8  = tx & 7;
        int kp  = k0 + (tx & ~7) + ((i8 < 4) ? 2 * i8 : 2 * (i8 - 4) + 1);
        #pragma unroll
        for (int j = 0; j < 32; j += 8)
            Wt[(size_t)(n0 + ty + j) * D_MODEL + kp] = to_tf32(tile[tx][ty + j]);
    } else {
        int c = (bid - PREP_WT) * 8 + (tid >> 5);
        int tau = tid & 31;
        float ft = (float)tau;
        float acc = 0.0f;
        #pragma unroll 8
        for (int n = 0; n < NSTATE; n++) {
            int idx = c * NSTATE + n;
            float re = lre[idx], im = lim[idx], bn = Bm[idx];
            float cr = cre[idx] * bn, ci = cim[idx] * bn;
            float s, co;
            sincosf(im * ft, &s, &co);
            acc += expf(re * ft) * (cr * co - ci * s);
        }
        g_k[c * NTAPS + tau] = acc;
    }
}

// ---------------------------------------------------------------------------
// Warp-MMA tf32 GEMM — EXACT R12 winner. CTA tile 128x128, BK=32, 8 warps
// (2m x 4n), m16n8k8, 2 CTAs/SM. 3-stage cp.async pipeline, literal buffer
// indices, running pointers, single barrier per stage. Pair-preserving
// XOR swizzle + k-interleaved operands -> LDS.64 fragment loads.
// ---------------------------------------------------------------------------
__device__ __forceinline__ float gelu_exact(float v) {
    return 0.5f * v * (1.0f + erff(v * 0.70710678118654752f));
}

#define STG_A 16384
#define STG_BYTES 32768                  // A(16KB) + B(16KB) per stage
#define NSTAGE 3
#define GEMM_SMEM (NSTAGE * STG_BYTES)   // 96KB

template<int EPI>
__global__ __launch_bounds__(256, 2)
void gemm_mma(const float* __restrict__ A, const float* __restrict__ Bt,
              const float* __restrict__ bias, const float* __restrict__ resid,
              float* __restrict__ C)
{
    extern __shared__ __align__(16) char sm[];
    uint32_t ubase = smem_u32(sm);

    int tid = threadIdx.x;
    int lane = tid & 31;
    int wid  = tid >> 5;
    int wm = wid >> 2;       // 0..1
    int wn = wid & 3;        // 0..3
    int g  = lane >> 2;      // 0..7
    int t4 = lane & 3;       // 0..3

    // hoisted fragment addressing (stage-invariant)
    uint32_t go[4];
    #pragma unroll
    for (int ks = 0; ks < 4; ks++)
        go[ks] = (uint32_t)((((2 * ks + (t4 >> 1)) ^ ((g & 3) << 1)) << 4) + ((t4 & 1) << 3));
    uint32_t aoff[4], boff[4];
    #pragma unroll
    for (int mt = 0; mt < 4; mt++) aoff[mt] = (wm * 64 + mt * 16 + g) * 128;
    #pragma unroll
    for (int nt = 0; nt < 4; nt++) boff[nt] = (wn * 32 + nt * 8 + g) * 128;

    int bn = blockIdx.x, bm = blockIdx.y;
    int rowA = bm * 128, rowB = bn * 128;

    // per-thread staging addresses: copy i adds constant row stride (32 rows)
    int crow = tid >> 3, c4 = tid & 7;
    uint32_t so0 = ubase + (uint32_t)(crow * 128 + ((c4 ^ ((crow & 3) << 1)) << 4));
    const float* aP = A  + (((size_t)(rowA + crow)) << 9) + (c4 << 2);
    const float* bP = Bt + (((size_t)(rowB + crow)) << 9) + (c4 << 2);

    float acc[4][4][4];
    #pragma unroll
    for (int mt = 0; mt < 4; mt++)
        #pragma unroll
        for (int nt = 0; nt < 4; nt++)
            #pragma unroll
            for (int q = 0; q < 4; q++) acc[mt][nt][q] = 0.0f;

    // prefetch one stage into buffer at byte offset BB; advances aP/bP by 32
    auto gprefetch = [&](uint32_t BB) {
        cp16(so0 + BB,                  aP);
        cp16(so0 + BB +  4096,          aP + 16384);
        cp16(so0 + BB +  8192,          aP + 32768);
        cp16(so0 + BB + 12288,          aP + 49152);
        cp16(so0 + BB + STG_A,          bP);
        cp16(so0 + BB + STG_A +  4096,  bP + 16384);
        cp16(so0 + BB + STG_A +  8192,  bP + 32768);
        cp16(so0 + BB + STG_A + 12288,  bP + 49152);
        aP += 32; bP += 32;
        CP_COMMIT();
    };

    auto gcompute = [&](const char* cA) {
        const char* cB = cA + STG_A;
        #pragma unroll
        for (int ks = 0; ks < 4; ks++) {
            float2 a0[4], a1[4], bb[4];
            #pragma unroll
            for (int mt = 0; mt < 4; mt++) {
                a0[mt] = *(const float2*)(cA + aoff[mt] + go[ks]);
                a1[mt] = *(const float2*)(cA + aoff[mt] + 1024 + go[ks]);
            }
            #pragma unroll
            for (int nt = 0; nt < 4; nt++)
                bb[nt] = *(const float2*)(cB + boff[nt] + go[ks]);
            #pragma unroll
            for (int mt = 0; mt < 4; mt++)
                #pragma unroll
                for (int nt = 0; nt < 4; nt++)
                    mma_tf32(acc[mt][nt], a0[mt].x, a1[mt].x, a0[mt].y, a1[mt].y,
                             bb[nt].x, bb[nt].y);
        }
    };

    // prologue: stage 0 -> buf0, stage 1 -> buf1
    gprefetch(0);
    gprefetch(STG_BYTES);

    // stages 0..11: 4 x (buf0, buf1, buf2), prefetching s+2 with literal bufs
    #pragma unroll 1
    for (int it = 0; it < 4; it++) {
        CP_WAIT(1); __syncthreads(); gprefetch(2 * STG_BYTES); gcompute(sm);
        CP_WAIT(1); __syncthreads(); gprefetch(0);             gcompute(sm + STG_BYTES);
        CP_WAIT(1); __syncthreads(); gprefetch(STG_BYTES);     gcompute(sm + 2 * STG_BYTES);
    }
    // s=12..15: two more prefetches then drain
    CP_WAIT(1); __syncthreads(); gprefetch(2 * STG_BYTES); gcompute(sm);
    CP_WAIT(1); __syncthreads(); gprefetch(0);             gcompute(sm + STG_BYTES);
    CP_WAIT(1); __syncthreads();                           gcompute(sm + 2 * STG_BYTES);
    CP_WAIT(0); __syncthreads();                           gcompute(sm);

    // epilogue
    #pragma unroll
    for (int mt = 0; mt < 4; mt++) {
        size_t r0 = (size_t)rowA + wm * 64 + mt * 16 + g;
        size_t r1 = r0 + 8;
        #pragma unroll
        for (int nt = 0; nt < 4; nt++) {
            int col = bn * 128 + wn * 32 + nt * 8 + 2 * t4;
            float b0 = bias[col], b1 = bias[col + 1];
            float v0 = acc[mt][nt][0] + b0;
            float v1 = acc[mt][nt][1] + b1;
            float v2 = acc[mt][nt][2] + b0;
            float v3 = acc[mt][nt][3] + b1;
            if (EPI == 1) {
                const float* rr0 = resid + r0 * D_MODEL + col;
                const float* rr1 = resid + r1 * D_MODEL + col;
                v0 = rr0[0] + gelu_exact(v0);
                v1 = rr0[1] + gelu_exact(v1);
                v2 = rr1[0] + gelu_exact(v2);
                v3 = rr1[1] + gelu_exact(v3);
            }
            *(float2*)(C + r0 * D_MODEL + col) = make_float2(v0, v1);
            *(float2*)(C + r1 * D_MODEL + col) = make_float2(v2, v3);
        }
    }
}

// ---------------------------------------------------------------------------
// Bidirectional 32-tap FIR + D skip. Block = 8 chunks x 256 rows, 256 threads
// (thread = 1 chunk x 8 rows). CIRCULAR register windows (compile-time slots,
// zero shift-MOVs), operands as ulonglong2 (f32x2 pairs register-aliased).
// Coalesced LDS.128; lane-pair shuffle assembles the k-interleave in regs ->
// one full-sector STG.128 per row.
// ---------------------------------------------------------------------------
#define FT_BLK 256
#define FIR_ROWS (FT_BLK + 2 * NTAPS + 1)   // 321

__global__ __launch_bounds__(256)
void fir_kernel(const float* __restrict__ Dvec)
{
    int c0 = blockIdx.y * 8;
    int b  = blockIdx.z;
    int t0 = blockIdx.x * FT_BLK;
    int tid = threadIdx.x;

    __shared__ float4 su[FIR_ROWS][8];   // [local row][chunk]
    __shared__ float  sk[8][33];         // padded taps

    const float4* u4 = (const float4*)g_z1;
    for (int slot = tid; slot < FIR_ROWS * 8; slot += 256) {
        int row = slot >> 3, cc = slot & 7;
        int t = t0 - 32 + row;
        float4 v = make_float4(0.f, 0.f, 0.f, 0.f);
        if (t >= 0 && t < L_SEQ) v = u4[((size_t)b * L_SEQ + t) * NC + c0 + cc];
        su[row][cc] = v;
    }
    {
        int cc = tid >> 5, tau = tid & 31;
        sk[cc][tau] = g_k[(c0 + cc) * NTAPS + tau];
    }
    __syncthreads();

    int c  = tid & 7;          // chunk within group
    int rg = tid >> 3;         // row group 0..31
    int w  = rg * 8;           // first output row (local)

    // circular windows: F[idx & 7] = u[w+idx], idx in [32-tau, 39-tau]
    //                   Bw[idx & 7] = u[w+idx], idx in [33+tau, 40+tau]
    ulonglong2 F[8], Bw[8];
    #pragma unroll
    for (int i = 0; i < 8; i++) {
        F[i]             = *(const ulonglong2*)&su[w + 32 + i][c];
        Bw[(33 + i) & 7] = *(const ulonglong2*)&su[w + 33 + i][c];
    }

    float dv = Dvec[c0 + c];
    uint64_t dv2 = pk2(dv, dv);
    uint64_t aL[8], aH[8];
    #pragma unroll
    for (int r = 0; r < 8; r++) {
        aL[r] = mulx2(dv2, F[r].x);
        aH[r] = mulx2(dv2, F[r].y);
    }

    #pragma unroll
    for (int tau = 0; tau < NTAPS; tau++) {
        float kt = sk[c][tau];
        uint64_t k2 = pk2(kt, kt);
        #pragma unroll
        for (int r = 0; r < 8; r++) {
            ulonglong2 fs = F[(32 + r - tau) & 7];   // u[w+32+r-tau]
            ulonglong2 bs = Bw[(33 + r + tau) & 7];  // u[w+33+r+tau]
            aL[r] = fmax2(k2, addx2(fs.x, bs.x), aL[r]);
            aH[r] = fmax2(k2, addx2(fs.y, bs.y), aH[r]);
        }
        if (tau < NTAPS - 1) {
            F[(31 - tau) & 7]  = *(const ulonglong2*)&su[w + 31 - tau][c];
            Bw[(41 + tau) & 7] = *(const ulonglong2*)&su[w + 41 + tau][c];
        }
    }

    // interleaved store: lane pairs (c, c^1) exchange halves, one STG.128/row
    float4* ybase = (float4*)(g_y) + (size_t)(c0 >> 1) * 2 + (c >> 1) * 2 + (c & 1);
    #pragma unroll
    for (int r = 0; r < 8; r++) {
        float4 o;
        upk2(aL[r], o.x, o.y);
        upk2(aH[r], o.z, o.w);
        o.x = to_tf32(o.x); o.y = to_tf32(o.y); o.z = to_tf32(o.z); o.w = to_tf32(o.w);
        float rx = __shfl_xor_sync(0xFFFFFFFFu, o.x, 1);
        float ry = __shfl_xor_sync(0xFFFFFFFFu, o.y, 1);
        float rz = __shfl_xor_sync(0xFFFFFFFFu, o.z, 1);
        float rw = __shfl_xor_sync(0xFFFFFFFFu, o.w, 1);
        float4 st = ((c & 1) == 0) ? make_float4(o.x, rx, o.y, ry)
                                   : make_float4(rz, o.z, rw, o.w);
        ybase[((size_t)b * L_SEQ + t0 + w + r) * (D_MODEL / 4)] = st;
    }
}

// ---------------------------------------------------------------------------
// Launch
// ---------------------------------------------------------------------------
extern "C" void kernel_launch(void* const* d_in, const int* in_sizes, int n_in,
                              void* d_out, int out_size)
{
    const float* x    = (const float*)d_in[0];
    const float* ln_g = (const float*)d_in[1];
    const float* ln_b = (const float*)d_in[2];
    const float* Win  = (const float*)d_in[3];
    const float* bin_ = (const float*)d_in[4];
    const float* Wout = (const float*)d_in[5];
    const float* bout = (const float*)d_in[6];
    const float* lre  = (const float*)d_in[7];
    const float* lim  = (const float*)d_in[8];
    const float* Bm   = (const float*)d_in[9];
    const float* cre  = (const float*)d_in[10];
    const float* cim  = (const float*)d_in[11];
    const float* Dvec = (const float*)d_in[12];
    float* out = (float*)d_out;

    float *z, *z1, *y, *wti, *wto;
    cudaGetSymbolAddress((void**)&z,   g_z);
    cudaGetSymbolAddress((void**)&z1,  g_z1);
    cudaGetSymbolAddress((void**)&y,   g_y);
    cudaGetSymbolAddress((void**)&wti, g_wti);
    cudaGetSymbolAddress((void**)&wto, g_wto);

    cudaFuncSetAttribute(gemm_mma<0>, cudaFuncAttributeMaxDynamicSharedMemorySize, GEMM_SMEM);
    cudaFuncSetAttribute(gemm_mma<1>, cudaFuncAttributeMaxDynamicSharedMemorySize, GEMM_SMEM);

    // 1. combined prep: LayerNorm + Win^T + Wout^T + FIR taps
    prep_kernel<<<PREP_TOTAL, 256>>>(x, ln_g, ln_b, Win, Wout, lre, lim, Bm, cre, cim);

    // 2. in-projection: z1 = z @ Win + bin
    gemm_mma<0><<<dim3(4, 256), 256, GEMM_SMEM>>>(z, wti, bin_, nullptr, z1);

    // 3. bidirectional FIR + D skip
    fir_kernel<<<dim3(L_SEQ / FT_BLK, NC / 8, B_SZ), 256>>>(Dvec);

    // 4. out-projection + gelu + residual -> d_out
    gemm_mma<1><<<dim3(4, 256), 256, GEMM_SMEM>>>(y, wto, bout, x, out);
}